// round 14
// baseline (speedup 1.0000x reference)
#include <cuda_runtime.h>
#include <stdint.h>

#define BB 4
#define NN 4096
#define DD 128
#define KK 2048
#define EPSV 1e-10f
#define RPB 4     // rows per gatherg block

// ---- scratch (no allocation allowed) ----
__device__ int   d_idx[BB * KK];
__device__ float d_vals[BB * KK];

// output layout: g_new | new_h | idx (float32)
#define OFF_G 0
#define OFF_H ((size_t)BB * KK * KK)
#define OFF_I (OFF_H + (size_t)BB * KK * DD)

__device__ __forceinline__ unsigned smem_u32(const void* p) {
    unsigned a;
    asm("{ .reg .u64 t; cvta.to.shared.u64 t, %1; cvt.u32.u64 %0, t; }" : "=r"(a) : "l"(p));
    return a;
}

// ---------------------------------------------------------------------------
// Kernel 1 (fused, no cross-block dependency): scores + exact rank-by-count.
// 32 blocks per batch x 1024 threads. Each block REDUNDANTLY computes all
// 4096 scores of its batch directly into smem (h is L2-resident after the
// first reader; 2 MB/batch), then ranks its own 128 nodes with 8 threads
// per node. No global key round-trip, no barrier, one launch.
// key = (sigmoid_bits << 32) | (0xFFFFFFFF - node): descending key order ==
// descending score, ascending node on ties (jax.lax.top_k semantics).
// ---------------------------------------------------------------------------
__global__ void __launch_bounds__(1024) select_kernel(const float4* __restrict__ h,
                                                      const float4* __restrict__ w,
                                                      const float* __restrict__ bptr) {
    __shared__ __align__(16) unsigned long long sk[NN];   // 32 KB
    __shared__ int part[7][128];                          // 3.5 KB
    const int b   = blockIdx.x >> 5;
    const int blk = blockIdx.x & 31;
    const int tid = threadIdx.x;
    const int wid = tid >> 5, lane = tid & 31;

    // ---- Phase A: all 4096 scores; warp w owns nodes [w*128, (w+1)*128) ----
    const float  bias = bptr[0];
    const float4 wv   = w[lane];
    #pragma unroll 2
    for (int s = 0; s < 16; s++) {
        const int n0 = wid * 128 + s * 8;                 // 8 nodes per step
        float sd[8];
        #pragma unroll
        for (int u = 0; u < 8; u++) {
            float4 a = h[((size_t)b * NN + n0 + u) * (DD / 4) + lane];
            sd[u] = a.x * wv.x + a.y * wv.y + a.z * wv.z + a.w * wv.w;
        }
        #pragma unroll
        for (int o = 16; o; o >>= 1) {
            #pragma unroll
            for (int u = 0; u < 8; u++) sd[u] += __shfl_xor_sync(0xFFFFFFFFu, sd[u], o);
        }
        if (lane < 8) {
            const int nd = n0 + lane;
            float sc = 1.0f / (1.0f + expf(-(sd[lane] + bias)));
            sk[nd] = ((unsigned long long)__float_as_uint(sc) << 32) |
                     (unsigned long long)(0xFFFFFFFFu - (unsigned)nd);
        }
    }
    __syncthreads();

    // ---- Phase B: rank own 128 nodes, 8 threads per node (512 keys each) ----
    const int node = blk * 128 + (tid & 127);
    const int e    = tid >> 7;
    const unsigned long long my = sk[node];
    const ulonglong2* sk2 = (const ulonglong2*)(sk + e * (NN / 8));
    int r = 0;
    #pragma unroll 8
    for (int i = 0; i < NN / 16; i++) {
        ulonglong2 kk = sk2[i];
        r += (kk.x > my) + (kk.y > my);
    }
    if (e) part[e - 1][tid & 127] = r;
    __syncthreads();
    if (!e) {
        #pragma unroll
        for (int p = 0; p < 7; p++) r += part[p][tid];
        if (r < KK) {
            d_idx [b * KK + r] = node;
            d_vals[b * KK + r] = __uint_as_float((unsigned int)(my >> 32));
        }
    }
}

// ---------------------------------------------------------------------------
// Kernel 2: gathered adjacency + degree normalize, fused new_h + idx.
// Exact R10/R13 version (measured best): 2-stage cp.async, lookahead 1,
// RPB=4, 512 threads, one STG.128 per thread per row.
// ---------------------------------------------------------------------------
__global__ void __launch_bounds__(512) gatherg_kernel(const float* __restrict__ g,
                                                      const float* __restrict__ h,
                                                      float* __restrict__ out) {
    __shared__ __align__(16) float buf[2][NN];              // 32 KB
    __shared__ float wsum[16];

    const int b    = blockIdx.y;
    const int base = blockIdx.x * RPB;
    const int tid  = threadIdx.x;

    auto issue_row = [&](int r, int st) {
        const int node = d_idx[b * KK + base + r];
        const char* gsrc = (const char*)(g + ((size_t)b * NN + node) * NN) + tid * 16;
        unsigned sdst = smem_u32(buf[st]) + tid * 16;
        #pragma unroll
        for (int c = 0; c < 2; c++) {
            asm volatile("cp.async.cg.shared.global [%0], [%1], 16;"
                         :: "r"(sdst + c * 8192), "l"(gsrc + c * 8192) : "memory");
        }
        asm volatile("cp.async.commit_group;" ::: "memory");
    };

    issue_row(0, 0);
    issue_row(1, 1);

    const int4 c0 = ((const int4*)(d_idx + b * KK))[tid];

    #pragma unroll
    for (int r = 0; r < RPB; r++) {
        const int   st   = r & 1;
        const int   row  = b * KK + base + r;
        const int   node = d_idx[row];
        const float v    = d_vals[row];

        if (tid < 32) {
            float4 hv = __ldg((const float4*)(h + ((size_t)b * NN + node) * DD) + tid);
            hv.x *= v; hv.y *= v; hv.z *= v; hv.w *= v;
            ((float4*)(out + OFF_H + (size_t)row * DD))[tid] = hv;
        }
        if (tid == 32) out[OFF_I + row] = (float)node;

        if (r < RPB - 1)
            asm volatile("cp.async.wait_group 1;" ::: "memory");
        else
            asm volatile("cp.async.wait_group 0;" ::: "memory");
        __syncthreads();

        const float* srow = buf[st];
        float vv[4];
        vv[0] = srow[c0.x]; vv[1] = srow[c0.y]; vv[2] = srow[c0.z]; vv[3] = srow[c0.w];
        float local = (vv[0] + vv[1]) + (vv[2] + vv[3]);
        #pragma unroll
        for (int o = 16; o; o >>= 1) local += __shfl_xor_sync(0xFFFFFFFFu, local, o);
        if ((tid & 31) == 0) wsum[tid >> 5] = local;
        __syncthreads();

        float deg = 0.f;
        #pragma unroll
        for (int wv = 0; wv < 16; wv++) deg += wsum[wv];
        const float inv = 1.0f / (deg + EPSV);

        if (r + 2 < RPB) issue_row(r + 2, st);

        float4* dst4 = (float4*)(out + OFF_G + (size_t)row * KK);
        dst4[tid] = make_float4(vv[0] * inv, vv[1] * inv, vv[2] * inv, vv[3] * inv);
    }
}

// ---------------------------------------------------------------------------
extern "C" void kernel_launch(void* const* d_in, const int* in_sizes, int n_in,
                              void* d_out, int out_size) {
    const float* g = (const float*)d_in[0];   // [B,N,N]
    const float* h = (const float*)d_in[1];   // [B,N,D]
    const float* w = (const float*)d_in[2];   // [D]
    const float* b = (const float*)d_in[3];   // scalar
    float* out = (float*)d_out;

    select_kernel<<<BB * 32, 1024>>>((const float4*)h, (const float4*)w, b);
    dim3 grid(KK / RPB, BB);
    gatherg_kernel<<<grid, 512>>>(g, h, out);
}

// round 15
// speedup vs baseline: 1.2957x; 1.2957x over previous
#include <cuda_runtime.h>
#include <stdint.h>

#define BB 4
#define NN 4096
#define DD 128
#define KK 2048
#define EPSV 1e-10f
#define RPB 4     // rows per gatherg block

// ---- scratch (no allocation allowed) ----
__device__ unsigned long long d_keys[BB * NN];   // 128 KB
__device__ int   d_idx[BB * KK];
__device__ float d_vals[BB * KK];

// output layout: g_new | new_h | idx (float32)
#define OFF_G 0
#define OFF_H ((size_t)BB * KK * KK)
#define OFF_I (OFF_H + (size_t)BB * KK * DD)

__device__ __forceinline__ unsigned smem_u32(const void* p) {
    unsigned a;
    asm("{ .reg .u64 t; cvta.to.shared.u64 t, %1; cvt.u32.u64 %0, t; }" : "=r"(a) : "l"(p));
    return a;
}
__device__ __forceinline__ void pdl_wait()    { asm volatile("griddepcontrol.wait;" ::: "memory"); }
__device__ __forceinline__ void pdl_trigger() { asm volatile("griddepcontrol.launch_dependents;" ::: "memory"); }

// ---------------------------------------------------------------------------
// Kernel 1: scores = sigmoid(h . w + b) packed into sortable u64 keys.
// key = (score_bits << 32) | (0xFFFFFFFF - node): descending key order ==
// descending score, ascending node on ties (jax.lax.top_k). 4 nodes/warp.
// ---------------------------------------------------------------------------
__global__ void __launch_bounds__(512) scores_kernel(const float4* __restrict__ h,
                                                     const float4* __restrict__ w,
                                                     const float* __restrict__ bptr) {
    int gwarp = (blockIdx.x * blockDim.x + threadIdx.x) >> 5;
    int lane  = threadIdx.x & 31;
    int n0 = gwarp * 4;
    if (n0 < BB * NN) {
        float4 wv = w[lane];
        float s[4];
        #pragma unroll
        for (int u = 0; u < 4; u++) {
            float4 a = h[(size_t)(n0 + u) * (DD / 4) + lane];
            s[u] = a.x * wv.x + a.y * wv.y + a.z * wv.z + a.w * wv.w;
        }
        #pragma unroll
        for (int o = 16; o; o >>= 1) {
            #pragma unroll
            for (int u = 0; u < 4; u++) s[u] += __shfl_xor_sync(0xFFFFFFFFu, s[u], o);
        }
        if (lane < 4) {
            int nd = n0 + lane;
            float x  = s[lane] + bptr[0];
            float sc = 1.0f / (1.0f + expf(-x));
            unsigned int sb = __float_as_uint(sc);
            unsigned int node = (unsigned int)(nd & (NN - 1));
            d_keys[nd] = ((unsigned long long)sb << 32) |
                         (unsigned long long)(0xFFFFFFFFu - node);
        }
    }
    pdl_trigger();                 // all stores issued; let rank launch
}

// ---------------------------------------------------------------------------
// Kernel 2: exact rank-by-count (keys unique). 1024 threads / 128 nodes per
// block: each node's compares split across EIGHT threads (512 keys each).
// ---------------------------------------------------------------------------
__global__ void __launch_bounds__(1024) rank_kernel() {
    __shared__ __align__(16) unsigned long long sk[NN];   // 32 KB
    __shared__ int part[7][128];
    const int b   = blockIdx.x >> 5;
    const int blk = blockIdx.x & 31;
    const int tid = threadIdx.x;

    pdl_wait();                    // d_keys must be visible from here on
    for (int i = tid; i < NN; i += 1024) sk[i] = d_keys[b * NN + i];
    __syncthreads();

    const int node = blk * 128 + (tid & 127);
    const int e    = tid >> 7;
    const unsigned long long my = sk[node];
    const ulonglong2* sk2 = (const ulonglong2*)(sk + e * (NN / 8));
    int r = 0;
    #pragma unroll 8
    for (int i = 0; i < NN / 16; i++) {
        ulonglong2 kk = sk2[i];
        r += (kk.x > my) + (kk.y > my);
    }
    if (e) part[e - 1][tid & 127] = r;
    __syncthreads();
    if (!e) {
        #pragma unroll
        for (int p = 0; p < 7; p++) r += part[p][tid];
        if (r < KK) {
            d_idx [b * KK + r] = node;
            d_vals[b * KK + r] = __uint_as_float((unsigned int)(my >> 32));
        }
    }
    pdl_trigger();                 // idx/vals stored; let gatherg launch
}

// ---------------------------------------------------------------------------
// Kernel 3: gathered adjacency + degree normalize, fused new_h + idx.
// Exact R13 pipeline: 2-stage cp.async, lookahead 1, RPB=4, 512 threads.
// ---------------------------------------------------------------------------
__global__ void __launch_bounds__(512) gatherg_kernel(const float* __restrict__ g,
                                                      const float* __restrict__ h,
                                                      float* __restrict__ out) {
    __shared__ __align__(16) float buf[2][NN];              // 32 KB
    __shared__ float wsum[16];

    const int b    = blockIdx.y;
    const int base = blockIdx.x * RPB;
    const int tid  = threadIdx.x;

    auto issue_row = [&](int r, int st) {
        const int node = d_idx[b * KK + base + r];
        const char* gsrc = (const char*)(g + ((size_t)b * NN + node) * NN) + tid * 16;
        unsigned sdst = smem_u32(buf[st]) + tid * 16;
        #pragma unroll
        for (int c = 0; c < 2; c++) {
            asm volatile("cp.async.cg.shared.global [%0], [%1], 16;"
                         :: "r"(sdst + c * 8192), "l"(gsrc + c * 8192) : "memory");
        }
        asm volatile("cp.async.commit_group;" ::: "memory");
    };

    pdl_wait();                    // d_idx/d_vals must be visible

    issue_row(0, 0);
    issue_row(1, 1);

    const int4 c0 = ((const int4*)(d_idx + b * KK))[tid];

    #pragma unroll
    for (int r = 0; r < RPB; r++) {
        const int   st   = r & 1;
        const int   row  = b * KK + base + r;
        const int   node = d_idx[row];
        const float v    = d_vals[row];

        if (tid < 32) {
            float4 hv = __ldg((const float4*)(h + ((size_t)b * NN + node) * DD) + tid);
            hv.x *= v; hv.y *= v; hv.z *= v; hv.w *= v;
            ((float4*)(out + OFF_H + (size_t)row * DD))[tid] = hv;
        }
        if (tid == 32) out[OFF_I + row] = (float)node;

        if (r < RPB - 1)
            asm volatile("cp.async.wait_group 1;" ::: "memory");
        else
            asm volatile("cp.async.wait_group 0;" ::: "memory");
        __syncthreads();

        const float* srow = buf[st];
        float vv[4];
        vv[0] = srow[c0.x]; vv[1] = srow[c0.y]; vv[2] = srow[c0.z]; vv[3] = srow[c0.w];
        float local = (vv[0] + vv[1]) + (vv[2] + vv[3]);
        #pragma unroll
        for (int o = 16; o; o >>= 1) local += __shfl_xor_sync(0xFFFFFFFFu, local, o);
        if ((tid & 31) == 0) wsum[tid >> 5] = local;
        __syncthreads();

        float deg = 0.f;
        #pragma unroll
        for (int wv = 0; wv < 16; wv++) deg += wsum[wv];
        const float inv = 1.0f / (deg + EPSV);

        if (r + 2 < RPB) issue_row(r + 2, st);

        float4* dst4 = (float4*)(out + OFF_G + (size_t)row * KK);
        dst4[tid] = make_float4(vv[0] * inv, vv[1] * inv, vv[2] * inv, vv[3] * inv);
    }
}

// ---------------------------------------------------------------------------
extern "C" void kernel_launch(void* const* d_in, const int* in_sizes, int n_in,
                              void* d_out, int out_size) {
    const float* g = (const float*)d_in[0];   // [B,N,N]
    const float* h = (const float*)d_in[1];   // [B,N,D]
    const float* w = (const float*)d_in[2];   // [D]
    const float* b = (const float*)d_in[3];   // scalar
    float* out = (float*)d_out;

    // scores: plain launch
    scores_kernel<<<(BB * NN) / 64, 512>>>((const float4*)h, (const float4*)w, b);

    // rank + gatherg: programmatic dependent launch (prologue overlaps
    // predecessor tail; griddepcontrol.wait guards the data dependency)
    cudaLaunchAttribute attr[1];
    attr[0].id = cudaLaunchAttributeProgrammaticStreamSerialization;
    attr[0].val.programmaticStreamSerializationAllowed = 1;

    {
        cudaLaunchConfig_t cfg = {};
        cfg.gridDim  = dim3(BB * 32);
        cfg.blockDim = dim3(1024);
        cfg.attrs = attr; cfg.numAttrs = 1;
        cudaLaunchKernelEx(&cfg, rank_kernel);
    }
    {
        cudaLaunchConfig_t cfg = {};
        cfg.gridDim  = dim3(KK / RPB, BB);
        cfg.blockDim = dim3(512);
        cfg.attrs = attr; cfg.numAttrs = 1;
        cudaLaunchKernelEx(&cfg, gatherg_kernel, g, h, out);
    }
}

// round 16
// speedup vs baseline: 1.4484x; 1.1179x over previous
#include <cuda_runtime.h>
#include <stdint.h>

#define BB 4
#define NN 4096
#define DD 128
#define KK 2048
#define EPSV 1e-10f
#define RPB 4     // rows per gatherg block

// ---- scratch (no allocation allowed) ----
__device__ unsigned long long d_keys[BB * NN];   // 128 KB
__device__ int   d_idx[BB * KK];
__device__ float d_vals[BB * KK];

// output layout: g_new | new_h | idx (float32)
#define OFF_G 0
#define OFF_H ((size_t)BB * KK * KK)
#define OFF_I (OFF_H + (size_t)BB * KK * DD)

__device__ __forceinline__ unsigned smem_u32(const void* p) {
    unsigned a;
    asm("{ .reg .u64 t; cvta.to.shared.u64 t, %1; cvt.u32.u64 %0, t; }" : "=r"(a) : "l"(p));
    return a;
}

// ---------------------------------------------------------------------------
// Kernel 1: scores = sigmoid(h . w + b) packed into sortable u64 keys.
// key = (score_bits << 32) | (0xFFFFFFFF - node): descending key order ==
// descending score, ascending node on ties (jax.lax.top_k). 4 nodes/warp.
// (R13 version.)
// ---------------------------------------------------------------------------
__global__ void __launch_bounds__(512) scores_kernel(const float4* __restrict__ h,
                                                     const float4* __restrict__ w,
                                                     const float* __restrict__ bptr) {
    int gwarp = (blockIdx.x * blockDim.x + threadIdx.x) >> 5;
    int lane  = threadIdx.x & 31;
    int n0 = gwarp * 4;
    if (n0 >= BB * NN) return;
    float4 wv = w[lane];
    float s[4];
    #pragma unroll
    for (int u = 0; u < 4; u++) {
        float4 a = h[(size_t)(n0 + u) * (DD / 4) + lane];
        s[u] = a.x * wv.x + a.y * wv.y + a.z * wv.z + a.w * wv.w;
    }
    #pragma unroll
    for (int o = 16; o; o >>= 1) {
        #pragma unroll
        for (int u = 0; u < 4; u++) s[u] += __shfl_xor_sync(0xFFFFFFFFu, s[u], o);
    }
    if (lane < 4) {
        int nd = n0 + lane;
        float x  = s[lane] + bptr[0];
        float sc = 1.0f / (1.0f + expf(-x));
        unsigned int sb = __float_as_uint(sc);
        unsigned int node = (unsigned int)(nd & (NN - 1));
        d_keys[nd] = ((unsigned long long)sb << 32) |
                     (unsigned long long)(0xFFFFFFFFu - node);
    }
}

// ---------------------------------------------------------------------------
// Kernel 2: exact rank-by-count (keys unique). 1024 threads / 128 nodes per
// block: each node's compares split across EIGHT threads. (R13 version.)
// ---------------------------------------------------------------------------
__global__ void __launch_bounds__(1024) rank_kernel() {
    __shared__ __align__(16) unsigned long long sk[NN];   // 32 KB
    __shared__ int part[7][128];
    const int b   = blockIdx.x >> 5;
    const int blk = blockIdx.x & 31;
    const int tid = threadIdx.x;
    for (int i = tid; i < NN; i += 1024) sk[i] = d_keys[b * NN + i];
    __syncthreads();

    const int node = blk * 128 + (tid & 127);
    const int e    = tid >> 7;
    const unsigned long long my = sk[node];
    const ulonglong2* sk2 = (const ulonglong2*)(sk + e * (NN / 8));
    int r = 0;
    #pragma unroll 8
    for (int i = 0; i < NN / 16; i++) {
        ulonglong2 kk = sk2[i];
        r += (kk.x > my) + (kk.y > my);
    }
    if (e) part[e - 1][tid & 127] = r;
    __syncthreads();
    if (!e) {
        #pragma unroll
        for (int p = 0; p < 7; p++) r += part[p][tid];
        if (r < KK) {
            d_idx [b * KK + r] = node;
            d_vals[b * KK + r] = __uint_as_float((unsigned int)(my >> 32));
        }
    }
}

// ---------------------------------------------------------------------------
// Kernel 3: gathered adjacency + degree normalize, fused new_h + idx.
// R13 input pipeline (2-stage cp.async, lookahead 1, RPB=4, 512 threads) but
// g_new rows leave via TMA BULK STORES from a double-buffered smem output
// tile: no per-thread STG wavefronts in l1tex for the 64 MB write stream.
// Dynamic smem: in[2][NN] (32 KB) + out[2][KK] (16 KB) = 48 KB.
// ---------------------------------------------------------------------------
__global__ void __launch_bounds__(512) gatherg_kernel(const float* __restrict__ g,
                                                      const float* __restrict__ h,
                                                      float* __restrict__ out) {
    extern __shared__ __align__(16) float dyn[];
    float* buf  = dyn;                    // [2][NN]
    float* obuf = dyn + 2 * NN;           // [2][KK]
    __shared__ float wsum[16];

    const int b    = blockIdx.y;
    const int base = blockIdx.x * RPB;
    const int tid  = threadIdx.x;
    const unsigned s_obuf = smem_u32(obuf);

    auto issue_row = [&](int r, int st) {
        const int node = d_idx[b * KK + base + r];
        const char* gsrc = (const char*)(g + ((size_t)b * NN + node) * NN) + tid * 16;
        unsigned sdst = smem_u32(buf) + st * (NN * 4) + tid * 16;
        #pragma unroll
        for (int c = 0; c < 2; c++) {
            asm volatile("cp.async.cg.shared.global [%0], [%1], 16;"
                         :: "r"(sdst + c * 8192), "l"(gsrc + c * 8192) : "memory");
        }
        asm volatile("cp.async.commit_group;" ::: "memory");
    };

    issue_row(0, 0);
    issue_row(1, 1);

    const int4 c0 = ((const int4*)(d_idx + b * KK))[tid];

    #pragma unroll
    for (int r = 0; r < RPB; r++) {
        const int   st   = r & 1;
        const int   row  = b * KK + base + r;
        const int   node = d_idx[row];
        const float v    = d_vals[row];

        // fused new_h + idx (independent of buffers; overlaps pending copies)
        if (tid < 32) {
            float4 hv = __ldg((const float4*)(h + ((size_t)b * NN + node) * DD) + tid);
            hv.x *= v; hv.y *= v; hv.z *= v; hv.w *= v;
            ((float4*)(out + OFF_H + (size_t)row * DD))[tid] = hv;
        }
        if (tid == 32) out[OFF_I + row] = (float)node;

        if (r < RPB - 1)
            asm volatile("cp.async.wait_group 1;" ::: "memory");
        else
            asm volatile("cp.async.wait_group 0;" ::: "memory");
        __syncthreads();

        const float* srow = buf + st * NN;
        float vv[4];
        vv[0] = srow[c0.x]; vv[1] = srow[c0.y]; vv[2] = srow[c0.z]; vv[3] = srow[c0.w];
        float local = (vv[0] + vv[1]) + (vv[2] + vv[3]);
        #pragma unroll
        for (int o = 16; o; o >>= 1) local += __shfl_xor_sync(0xFFFFFFFFu, local, o);
        if ((tid & 31) == 0) wsum[tid >> 5] = local;
        // obuf[st] reused from row r-2: its bulk store must have been read out
        if (tid == 0 && r >= 2)
            asm volatile("cp.async.bulk.wait_group.read 1;" ::: "memory");
        __syncthreads();                  // wsum visible + obuf[st] safe

        float deg = 0.f;
        #pragma unroll
        for (int wv = 0; wv < 16; wv++) deg += wsum[wv];
        const float inv = 1.0f / (deg + EPSV);

        if (r + 2 < RPB) issue_row(r + 2, st);   // refill input pipeline

        // stage normalized row into smem output tile (STS.128, conflict-free)
        ((float4*)(obuf + st * KK))[tid] =
            make_float4(vv[0] * inv, vv[1] * inv, vv[2] * inv, vv[3] * inv);
        __syncthreads();                  // output tile complete

        if (tid == 0) {
            asm volatile("fence.proxy.async.shared::cta;" ::: "memory");
            asm volatile("cp.async.bulk.global.shared::cta.bulk_group [%0], [%1], %2;"
                         :: "l"(out + OFF_G + (size_t)row * KK),
                            "r"(s_obuf + st * (KK * 4)), "r"(KK * 4) : "memory");
            asm volatile("cp.async.bulk.commit_group;" ::: "memory");
        }
    }
    // drain all bulk stores before exit
    if (tid == 0)
        asm volatile("cp.async.bulk.wait_group 0;" ::: "memory");
}

// ---------------------------------------------------------------------------
extern "C" void kernel_launch(void* const* d_in, const int* in_sizes, int n_in,
                              void* d_out, int out_size) {
    const float* g = (const float*)d_in[0];   // [B,N,N]
    const float* h = (const float*)d_in[1];   // [B,N,D]
    const float* w = (const float*)d_in[2];   // [D]
    const float* b = (const float*)d_in[3];   // scalar
    float* out = (float*)d_out;

    const int smem_bytes = (2 * NN + 2 * KK) * 4;   // 48 KB dynamic
    static bool attr_set = false;
    if (!attr_set) {
        cudaFuncSetAttribute(gatherg_kernel,
                             cudaFuncAttributeMaxDynamicSharedMemorySize, smem_bytes);
        attr_set = true;
    }

    scores_kernel<<<(BB * NN) / 64, 512>>>((const float4*)h, (const float4*)w, b);
    rank_kernel<<<BB * 32, 1024>>>();
    dim3 grid(KK / RPB, BB);
    gatherg_kernel<<<grid, 512, smem_bytes>>>(g, h, out);
}

// round 17
// speedup vs baseline: 1.5391x; 1.0626x over previous
#include <cuda_runtime.h>
#include <stdint.h>

#define BB 4
#define NN 4096
#define DD 128
#define KK 2048
#define EPSV 1e-10f
#define RPB 2     // rows per gatherg block (finer grid -> smaller tail)

// ---- scratch (no allocation allowed) ----
__device__ unsigned long long d_keys[BB * NN];   // 128 KB
__device__ int   d_idx[BB * KK];
__device__ float d_vals[BB * KK];

// output layout: g_new | new_h | idx (float32)
#define OFF_G 0
#define OFF_H ((size_t)BB * KK * KK)
#define OFF_I (OFF_H + (size_t)BB * KK * DD)

__device__ __forceinline__ unsigned smem_u32(const void* p) {
    unsigned a;
    asm("{ .reg .u64 t; cvta.to.shared.u64 t, %1; cvt.u32.u64 %0, t; }" : "=r"(a) : "l"(p));
    return a;
}

// ---------------------------------------------------------------------------
// Kernel 1: scores = sigmoid(h . w + b) packed into sortable u64 keys.
// key = (score_bits << 32) | (0xFFFFFFFF - node): descending key order ==
// descending score, ascending node on ties (jax.lax.top_k). 4 nodes/warp.
// (R13 version — measured best.)
// ---------------------------------------------------------------------------
__global__ void __launch_bounds__(512) scores_kernel(const float4* __restrict__ h,
                                                     const float4* __restrict__ w,
                                                     const float* __restrict__ bptr) {
    int gwarp = (blockIdx.x * blockDim.x + threadIdx.x) >> 5;
    int lane  = threadIdx.x & 31;
    int n0 = gwarp * 4;
    if (n0 >= BB * NN) return;
    float4 wv = w[lane];
    float s[4];
    #pragma unroll
    for (int u = 0; u < 4; u++) {
        float4 a = h[(size_t)(n0 + u) * (DD / 4) + lane];
        s[u] = a.x * wv.x + a.y * wv.y + a.z * wv.z + a.w * wv.w;
    }
    #pragma unroll
    for (int o = 16; o; o >>= 1) {
        #pragma unroll
        for (int u = 0; u < 4; u++) s[u] += __shfl_xor_sync(0xFFFFFFFFu, s[u], o);
    }
    if (lane < 4) {
        int nd = n0 + lane;
        float x  = s[lane] + bptr[0];
        float sc = 1.0f / (1.0f + expf(-x));
        unsigned int sb = __float_as_uint(sc);
        unsigned int node = (unsigned int)(nd & (NN - 1));
        d_keys[nd] = ((unsigned long long)sb << 32) |
                     (unsigned long long)(0xFFFFFFFFu - node);
    }
}

// ---------------------------------------------------------------------------
// Kernel 2: exact rank-by-count (keys unique). 1024 threads / 128 nodes per
// block: each node's compares split across EIGHT threads (512 keys each).
// (R13 version — measured best.)
// ---------------------------------------------------------------------------
__global__ void __launch_bounds__(1024) rank_kernel() {
    __shared__ __align__(16) unsigned long long sk[NN];   // 32 KB
    __shared__ int part[7][128];
    const int b   = blockIdx.x >> 5;
    const int blk = blockIdx.x & 31;
    const int tid = threadIdx.x;
    for (int i = tid; i < NN; i += 1024) sk[i] = d_keys[b * NN + i];
    __syncthreads();

    const int node = blk * 128 + (tid & 127);
    const int e    = tid >> 7;
    const unsigned long long my = sk[node];
    const ulonglong2* sk2 = (const ulonglong2*)(sk + e * (NN / 8));
    int r = 0;
    #pragma unroll 8
    for (int i = 0; i < NN / 16; i++) {
        ulonglong2 kk = sk2[i];
        r += (kk.x > my) + (kk.y > my);
    }
    if (e) part[e - 1][tid & 127] = r;
    __syncthreads();
    if (!e) {
        #pragma unroll
        for (int p = 0; p < 7; p++) r += part[p][tid];
        if (r < KK) {
            d_idx [b * KK + r] = node;
            d_vals[b * KK + r] = __uint_as_float((unsigned int)(my >> 32));
        }
    }
}

// ---------------------------------------------------------------------------
// Kernel 3: gathered adjacency + degree normalize, fused new_h + idx.
// R13 pipeline (2-stage cp.async, 512 threads) at RPB=2: both rows issued up
// front, 4096 blocks -> finer scheduling granularity, ~7% final-wave tail.
// ---------------------------------------------------------------------------
__global__ void __launch_bounds__(512) gatherg_kernel(const float* __restrict__ g,
                                                      const float* __restrict__ h,
                                                      float* __restrict__ out) {
    __shared__ __align__(16) float buf[2][NN];              // 32 KB
    __shared__ float wsum[16];

    const int b    = blockIdx.y;
    const int base = blockIdx.x * RPB;
    const int tid  = threadIdx.x;

    auto issue_row = [&](int r, int st) {
        const int node = d_idx[b * KK + base + r];
        const char* gsrc = (const char*)(g + ((size_t)b * NN + node) * NN) + tid * 16;
        unsigned sdst = smem_u32(buf[st]) + tid * 16;
        #pragma unroll
        for (int c = 0; c < 2; c++) {
            asm volatile("cp.async.cg.shared.global [%0], [%1], 16;"
                         :: "r"(sdst + c * 8192), "l"(gsrc + c * 8192) : "memory");
        }
        asm volatile("cp.async.commit_group;" ::: "memory");
    };

    issue_row(0, 0);
    issue_row(1, 1);

    const int4 c0 = ((const int4*)(d_idx + b * KK))[tid];

    #pragma unroll
    for (int r = 0; r < RPB; r++) {
        const int   st   = r & 1;
        const int   row  = b * KK + base + r;
        const int   node = d_idx[row];
        const float v    = d_vals[row];

        // fused new_h + idx (independent of buf; overlaps pending copies)
        if (tid < 32) {
            float4 hv = __ldg((const float4*)(h + ((size_t)b * NN + node) * DD) + tid);
            hv.x *= v; hv.y *= v; hv.z *= v; hv.w *= v;
            ((float4*)(out + OFF_H + (size_t)row * DD))[tid] = hv;
        }
        if (tid == 32) out[OFF_I + row] = (float)node;

        if (r < RPB - 1)
            asm volatile("cp.async.wait_group 1;" ::: "memory");
        else
            asm volatile("cp.async.wait_group 0;" ::: "memory");
        __syncthreads();

        const float* srow = buf[st];
        float vv[4];
        vv[0] = srow[c0.x]; vv[1] = srow[c0.y]; vv[2] = srow[c0.z]; vv[3] = srow[c0.w];
        float local = (vv[0] + vv[1]) + (vv[2] + vv[3]);
        #pragma unroll
        for (int o = 16; o; o >>= 1) local += __shfl_xor_sync(0xFFFFFFFFu, local, o);
        if ((tid & 31) == 0) wsum[tid >> 5] = local;
        __syncthreads();

        float deg = 0.f;
        #pragma unroll
        for (int wv = 0; wv < 16; wv++) deg += wsum[wv];
        const float inv = 1.0f / (deg + EPSV);

        float4* dst4 = (float4*)(out + OFF_G + (size_t)row * KK);
        dst4[tid] = make_float4(vv[0] * inv, vv[1] * inv, vv[2] * inv, vv[3] * inv);
    }
}

// ---------------------------------------------------------------------------
extern "C" void kernel_launch(void* const* d_in, const int* in_sizes, int n_in,
                              void* d_out, int out_size) {
    const float* g = (const float*)d_in[0];   // [B,N,N]
    const float* h = (const float*)d_in[1];   // [B,N,D]
    const float* w = (const float*)d_in[2];   // [D]
    const float* b = (const float*)d_in[3];   // scalar
    float* out = (float*)d_out;

    scores_kernel<<<(BB * NN) / 64, 512>>>((const float4*)h, (const float4*)w, b);
    rank_kernel<<<BB * 32, 1024>>>();
    dim3 grid(KK / RPB, BB);
    gatherg_kernel<<<grid, 512>>>(g, h, out);
}